// round 5
// baseline (speedup 1.0000x reference)
#include <cuda_runtime.h>
#include <cuda_bf16.h>
#include <math.h>
#include <stdint.h>

#define BATCH 256
#define SEQ   256
#define EMB   1024
#define HID   1024
#define NCLS  32000
#define G4    4096          // 4 gates * HID
#define WROW  2048          // EMB + HID
#define HB    (BATCH*HID)   // 262144
#define HB2   (2*BATCH*HID) // 524288 (2 dirs)
#define KS    32            // K chunk per stage
#define NCH   32            // 1024 / 32 chunks
#define NSTG  4             // pipeline stages
#define STGB  8192          // bytes per stage tile (128 rows x 32 bf16)
#define SMB_B 32768         // B region offset
#define PREW  132           // pre[] row stride in floats
#define SM_TOKS 67584
#define SMEMSZ  69632

// Scratch (device globals: allocation-free rule)
static __device__ float          g_XWf[(size_t)2 * SEQ * BATCH * G4]; // fp32 preact+bias [d][t][b][col*4+gi]
static __device__ __nv_bfloat16  g_Cb[(size_t)NCLS * EMB];
static __device__ __nv_bfloat16  g_Whb[(size_t)2 * G4 * HID];   // [d][col*4+gi][k]
static __device__ __nv_bfloat16  g_Wxb[(size_t)2 * G4 * EMB];   // [d][col*4+gi][k]
static __device__ __nv_bfloat16  g_hb[2 * HB2];                 // [pingpong][dir][b][col]
static __device__ float          g_c[HB2];
static __device__ float          g_hsum[HB];
static __device__ float          g_biasI[2 * G4];

// ---------------------------------------------------------------------------
__device__ __forceinline__ uint32_t smem_u32(const void* p) {
    uint32_t a;
    asm("{ .reg .u64 t; cvta.to.shared.u64 t, %1; cvt.u32.u64 %0, t; }" : "=r"(a) : "l"(p));
    return a;
}
__device__ __forceinline__ void cp16(uint32_t s, const void* g) {
    asm volatile("cp.async.ca.shared.global [%0], [%1], 16;"
                 :: "r"(s), "l"(__cvta_generic_to_global(g)) : "memory");
}
#define CP_COMMIT() asm volatile("cp.async.commit_group;" ::: "memory")
#define CP_WAIT(n)  asm volatile("cp.async.wait_group %0;" :: "n"(n) : "memory")

#define LDSM4(R, A) \
    asm volatile("ldmatrix.sync.aligned.m8n8.x4.shared.b16 {%0,%1,%2,%3}, [%4];" \
        : "=r"((R)[0]), "=r"((R)[1]), "=r"((R)[2]), "=r"((R)[3]) : "r"(A))

__device__ __forceinline__ void mma_bf16(float* d, const uint32_t* a, const uint32_t* b)
{
    asm volatile(
        "mma.sync.aligned.m16n8k16.row.col.f32.bf16.bf16.f32 "
        "{%0,%1,%2,%3}, {%4,%5,%6,%7}, {%8,%9}, {%0,%1,%2,%3};\n"
        : "+f"(d[0]), "+f"(d[1]), "+f"(d[2]), "+f"(d[3])
        : "r"(a[0]), "r"(a[1]), "r"(a[2]), "r"(a[3]), "r"(b[0]), "r"(b[1]));
}

// 16B-slot layout for a 128x32-bf16 stage tile: row r (0..127), chunk c (0..3).
// slot = 4r + (c ^ ((r>>1)&3)); byte = slot*16. For 8 consecutive rows at fixed
// c, slots hit all 8 distinct 16B bank groups -> conflict-free LDSM & STS.
__device__ __forceinline__ uint32_t slotb(int r, int c) {
    return (uint32_t)((r << 6) + ((c ^ ((r >> 1) & 3)) << 4));
}

// ---------------------------------------------------------------------------
// GEMM mainloop: block 128x128, 8 warps (2m x 4n), warp tile 64x32, KS=32,
// 4-stage cp.async pipeline, ldmatrix fragments. Leaves result in acc[16][4].
// aRow/bRow: this thread's load row base pointers (k-contiguous bf16).
// ---------------------------------------------------------------------------
__device__ __forceinline__ void hmma_mainloop(
    uint32_t smb, const __nv_bfloat16* aRow, const __nv_bfloat16* bRow,
    float (&acc)[16][4])
{
    const int tid  = threadIdx.x;
    const int lane = tid & 31, warp = tid >> 5;
    const int m0 = (warp >> 2) * 64, n0 = (warp & 3) * 32;

    // Loader slots: thread t loads row r = t>>1, chunks c0 = (t&1)*2, c0+1.
    const int rL = tid >> 1, cL = (tid & 1) * 2;
    const uint32_t sa0 = smb + slotb(rL, cL);
    const uint32_t sa1 = smb + slotb(rL, cL + 1);
    const uint32_t sb0 = smb + SMB_B + slotb(rL, cL);
    const uint32_t sb1 = smb + SMB_B + slotb(rL, cL + 1);
    const __nv_bfloat16* gA = aRow + cL * 8;
    const __nv_bfloat16* gB = bRow + cL * 8;

    // LDSM lane addresses (stage 0, kk = 0).
    uint32_t aAddr[4], bAddr[2];
#pragma unroll
    for (int mi = 0; mi < 4; ++mi)
        aAddr[mi] = smb + slotb(m0 + mi * 16 + (lane & 15), lane >> 4);
#pragma unroll
    for (int p = 0; p < 2; ++p)
        bAddr[p] = smb + SMB_B
                 + slotb(n0 + (2 * p + ((lane >> 4) & 1)) * 8 + (lane & 7), (lane >> 3) & 1);

    // Prologue: stages 0..2
#pragma unroll
    for (int st = 0; st < NSTG - 1; ++st) {
        const int kb = st * KS;
        cp16(sa0 + st * STGB, gA + kb);
        cp16(sa1 + st * STGB, gA + kb + 8);
        cp16(sb0 + st * STGB, gB + kb);
        cp16(sb1 + st * STGB, gB + kb + 8);
        CP_COMMIT();
    }

    for (int ch = 0; ch < NCH; ++ch) {
        CP_WAIT(2);
        __syncthreads();
        if (ch + NSTG - 1 < NCH) {
            const int st = (ch + NSTG - 1) & (NSTG - 1);
            const int kb = (ch + NSTG - 1) * KS;
            cp16(sa0 + st * STGB, gA + kb);
            cp16(sa1 + st * STGB, gA + kb + 8);
            cp16(sb0 + st * STGB, gB + kb);
            cp16(sb1 + st * STGB, gB + kb + 8);
        }
        CP_COMMIT();

        const uint32_t soff = (uint32_t)((ch & (NSTG - 1)) * STGB);
#pragma unroll
        for (int kk = 0; kk < 2; ++kk) {
            const uint32_t x = kk ? 32u : 0u;
            uint32_t af[4][4], bf[2][4];
#pragma unroll
            for (int mi = 0; mi < 4; ++mi) LDSM4(af[mi], (aAddr[mi] + soff) ^ x);
#pragma unroll
            for (int p = 0; p < 2; ++p)    LDSM4(bf[p], (bAddr[p] + soff) ^ x);
#pragma unroll
            for (int mi = 0; mi < 4; ++mi)
#pragma unroll
                for (int ni = 0; ni < 4; ++ni)
                    mma_bf16(acc[mi * 4 + ni], af[mi], &bf[ni >> 1][(ni & 1) * 2]);
        }
    }
    __syncthreads();   // safe to reuse smem after this
}

// ---------------------------------------------------------------------------
// init / conversions
// ---------------------------------------------------------------------------
__global__ void init_kernel()
{
    int i = blockIdx.x * blockDim.x + threadIdx.x;
    if (i < HB2) g_c[i] = 0.f;
    if (i < HB2) reinterpret_cast<uint32_t*>(g_hb)[i] = 0u;
}

__global__ __launch_bounds__(256) void convw_kernel(
    const float* __restrict__ W0, const float* __restrict__ W1,
    const float* __restrict__ W2, const float* __restrict__ W3,
    const float* __restrict__ W4, const float* __restrict__ W5,
    const float* __restrict__ W6, const float* __restrict__ W7)
{
    const float* Ws[8] = {W0,W1,W2,W3,W4,W5,W6,W7};
    int r = blockIdx.x;             // 0..16383
    int k = threadIdx.x * 4;
    const float* src;
    __nv_bfloat16* dst;
    if (r < 8192) {
        int d = r >> 12, np = r & 4095, gi = np & 3, col = np >> 2;
        src = Ws[d*4 + gi] + (size_t)col * WROW + EMB + k;
        dst = g_Whb + (size_t)r * HID + k;
    } else {
        int rr = r - 8192;
        int d = rr >> 12, np = rr & 4095, gi = np & 3, col = np >> 2;
        src = Ws[d*4 + gi] + (size_t)col * WROW + k;
        dst = g_Wxb + (size_t)rr * EMB + k;
    }
    float4 v = *(const float4*)src;
    __nv_bfloat162 lo; lo.x = __float2bfloat16(v.x); lo.y = __float2bfloat16(v.y);
    __nv_bfloat162 hi; hi.x = __float2bfloat16(v.z); hi.y = __float2bfloat16(v.w);
    *reinterpret_cast<__nv_bfloat162*>(dst)     = lo;
    *reinterpret_cast<__nv_bfloat162*>(dst + 2) = hi;
}

__global__ __launch_bounds__(256) void convc_kernel(const float* __restrict__ C)
{
    size_t row = blockIdx.x;
    int k = threadIdx.x * 4;
    float4 v = *(const float4*)(C + row * EMB + k);
    __nv_bfloat16* dst = g_Cb + row * EMB + k;
    __nv_bfloat162 lo; lo.x = __float2bfloat16(v.x); lo.y = __float2bfloat16(v.y);
    __nv_bfloat162 hi; hi.x = __float2bfloat16(v.z); hi.y = __float2bfloat16(v.w);
    *reinterpret_cast<__nv_bfloat162*>(dst)     = lo;
    *reinterpret_cast<__nv_bfloat162*>(dst + 2) = hi;
}

__global__ void bias_kernel(
    const float* __restrict__ B0, const float* __restrict__ B1,
    const float* __restrict__ B2, const float* __restrict__ B3,
    const float* __restrict__ B4, const float* __restrict__ B5,
    const float* __restrict__ B6, const float* __restrict__ B7)
{
    const float* Bs[8] = {B0,B1,B2,B3,B4,B5,B6,B7};
    int n = blockIdx.x * blockDim.x + threadIdx.x;
    if (n < 2 * G4) {
        int d = n >> 12, rr = n & 4095, gi = rr & 3, col = rr >> 2;
        g_biasI[n] = Bs[d*4 + gi][col];
    }
}

// ---------------------------------------------------------------------------
// xproj: XWf = gathered C[X] @ Wx^T + bias (fp32 out).
// M=65536 (m=t*256+b), N=8192 (n = d*4096 + col*4+gi), K=1024.
// ---------------------------------------------------------------------------
__global__ __launch_bounds__(256) void xproj_hm(const int* __restrict__ X)
{
    extern __shared__ __align__(16) char sm[];
    const uint32_t smb = smem_u32(sm);
    const int tid = threadIdx.x;
    const int nbase = blockIdx.x * 128;
    const int mbase = blockIdx.y * 128;

    if (tid < 128) {
        int m = mbase + tid;
        ((int*)(sm + SM_TOKS))[tid] = X[(m & 255) * SEQ + (m >> 8)];   // X[b][t]
    }
    __syncthreads();

    const __nv_bfloat16* aRow = g_Cb + (size_t)((int*)(sm + SM_TOKS))[tid >> 1] * EMB;
    const __nv_bfloat16* bRow = g_Wxb + (size_t)(nbase + (tid >> 1)) * EMB;

    float acc[16][4];
#pragma unroll
    for (int i = 0; i < 16; ++i)
#pragma unroll
        for (int j = 0; j < 4; ++j) acc[i][j] = 0.f;

    hmma_mainloop(smb, aRow, bRow, acc);

    // Epilogue: acc + bias -> g_XWf (fp32, scattered float2)
    const int lane = tid & 31, warp = tid >> 5;
    const int g = lane >> 2, q = lane & 3;
    const int m0 = (warp >> 2) * 64, n0 = (warp & 3) * 32;
    const int dd = nbase >> 12;
    float2 bias2[4];
#pragma unroll
    for (int ni = 0; ni < 4; ++ni)
        bias2[ni] = *reinterpret_cast<const float2*>(
            g_biasI + (size_t)dd * G4 + (nbase & 4095) + n0 + ni * 8 + 2 * q);

#pragma unroll
    for (int mi = 0; mi < 4; ++mi) {
        int m = mbase + m0 + mi * 16 + g;
        int t = m >> 8, b = m & 255;
        size_t rowbase = ((size_t)(dd * SEQ + t) * BATCH + b) * G4 + (nbase & 4095);
#pragma unroll
        for (int ni = 0; ni < 4; ++ni) {
            size_t off = rowbase + n0 + ni * 8 + 2 * q;
            float2 v0, v1;
            v0.x = acc[mi*4+ni][0] + bias2[ni].x;
            v0.y = acc[mi*4+ni][1] + bias2[ni].y;
            v1.x = acc[mi*4+ni][2] + bias2[ni].x;
            v1.y = acc[mi*4+ni][3] + bias2[ni].y;
            *reinterpret_cast<float2*>(g_XWf + off)            = v0;   // row b
            *reinterpret_cast<float2*>(g_XWf + off + 8 * G4)   = v1;   // row b+8
        }
    }
}

// ---------------------------------------------------------------------------
// step: h@Wh^T + fused LSTM cell. M=256(batch), N=4096 gate-interleaved/dir.
// grid (32, 2, 2): nbase, mbase, dir.
// ---------------------------------------------------------------------------
__global__ __launch_bounds__(256) void step_hm(int s)
{
    extern __shared__ __align__(16) char sm[];
    const uint32_t smb = smem_u32(sm);
    float* pre = reinterpret_cast<float*>(sm);   // reused after mainloop
    const int tid = threadIdx.x;
    const int d     = blockIdx.z;
    const int nbase = blockIdx.x * 128;
    const int mbase = blockIdx.y * 128;
    const int rb = s & 1, wb = rb ^ 1;

    const __nv_bfloat16* aRow = g_hb + (size_t)rb * HB2 + (size_t)d * HB
                                     + (size_t)(mbase + (tid >> 1)) * HID;
    const __nv_bfloat16* bRow = g_Whb + ((size_t)d * G4 + nbase + (tid >> 1)) * HID;

    float acc[16][4];
#pragma unroll
    for (int i = 0; i < 16; ++i)
#pragma unroll
        for (int j = 0; j < 4; ++j) acc[i][j] = 0.f;

    hmma_mainloop(smb, aRow, bRow, acc);

    // Stage preacts into smem (fp32, row stride PREW)
    const int lane = tid & 31, warp = tid >> 5;
    const int g = lane >> 2, q = lane & 3;
    const int m0 = (warp >> 2) * 64, n0 = (warp & 3) * 32;
#pragma unroll
    for (int mi = 0; mi < 4; ++mi) {
        int r = m0 + mi * 16 + g;
#pragma unroll
        for (int ni = 0; ni < 4; ++ni) {
            int c = n0 + ni * 8 + 2 * q;
            *reinterpret_cast<float2*>(&pre[r * PREW + c]) =
                make_float2(acc[mi*4+ni][0], acc[mi*4+ni][1]);
            *reinterpret_cast<float2*>(&pre[(r + 8) * PREW + c]) =
                make_float2(acc[mi*4+ni][2], acc[mi*4+ni][3]);
        }
    }
    __syncthreads();

    // Cell pass: thread t -> batch row r = t&127, half = t>>7 (16 cells each).
    {
        const int r    = tid & 127;
        const int half = tid >> 7;
        const int b    = mbase + r;
        const int tt   = d ? (SEQ - 1 - s) : s;
        const float* prow = pre + r * PREW + half * 64;
        const float* xwp  = g_XWf + ((size_t)(d * SEQ + tt) * BATCH + b) * G4
                                  + nbase + half * 64;
        float* cp = g_c + (size_t)d * HB + (size_t)b * HID + (nbase >> 2) + half * 16;
        __nv_bfloat16* hp = g_hb + (size_t)wb * HB2 + (size_t)d * HB
                                 + (size_t)b * HID + (nbase >> 2) + half * 16;
        uint32_t hbuf[8];
#pragma unroll
        for (int j = 0; j < 16; ++j) {
            float4 p  = *reinterpret_cast<const float4*>(prow + 4 * j);
            float4 xw = *reinterpret_cast<const float4*>(xwp  + 4 * j);
            float pi = p.x + xw.x;
            float pf = p.y + xw.y;
            float po = p.z + xw.z;
            float pg = p.w + xw.w;
            float ig = 1.f / (1.f + expf(-pi));
            float fg = 1.f / (1.f + expf(-pf));
            float og = 1.f / (1.f + expf(-po));
            float gv = tanhf(pg);
            float cc = fg * cp[j] + ig * gv;
            cp[j] = cc;
            float hv = og * tanhf(cc);
            __nv_bfloat16 hb16 = __float2bfloat16(hv);
            uint16_t raw = *reinterpret_cast<uint16_t*>(&hb16);
            if (j & 1) hbuf[j >> 1] |= ((uint32_t)raw) << 16;
            else       hbuf[j >> 1]  = raw;
        }
        *reinterpret_cast<uint4*>(hp)     = *reinterpret_cast<uint4*>(&hbuf[0]);
        *reinterpret_cast<uint4*>(hp + 8) = *reinterpret_cast<uint4*>(&hbuf[4]);
    }
}

// ---------------------------------------------------------------------------
__global__ void hsum_kernel()
{
    int i = blockIdx.x * blockDim.x + threadIdx.x;
    if (i < HB)
        g_hsum[i] = __bfloat162float(g_hb[i]) + __bfloat162float(g_hb[HB + i]);
}

// ---------------------------------------------------------------------------
// Output GEMM in fp32 FFMA (precision): M=256, N=32000, K=1024.
// ---------------------------------------------------------------------------
__global__ __launch_bounds__(256) void out_kernel(
    const float* __restrict__ Wout, const float* __restrict__ bout,
    float* __restrict__ out)
{
    __shared__ __align__(16) float As[2][8][128];
    __shared__ __align__(16) float Bs[2][8][128];

    const int tid   = threadIdx.x;
    const int nbase = blockIdx.x * 128;
    const int mbase = blockIdx.y * 128;

    const int a_m = tid >> 1, a_k = (tid & 1) * 4;
    const int b_n = tid >> 1, b_k = (tid & 1) * 4;
    const float* aptr = g_hsum + (size_t)(mbase + a_m) * HID;
    const float* bptr = Wout + (size_t)(nbase + b_n) * HID;

    float acc[8][8];
#pragma unroll
    for (int i = 0; i < 8; ++i)
#pragma unroll
        for (int j = 0; j < 8; ++j) acc[i][j] = 0.f;

    const int r0 = (tid >> 4) * 8;
    const int c0 = (tid & 15) * 8;

    float4 pa = *(const float4*)(aptr + a_k);
    float4 pb = *(const float4*)(bptr + b_k);
    As[0][a_k+0][a_m]=pa.x; As[0][a_k+1][a_m]=pa.y; As[0][a_k+2][a_m]=pa.z; As[0][a_k+3][a_m]=pa.w;
    Bs[0][b_k+0][b_n]=pb.x; Bs[0][b_k+1][b_n]=pb.y; Bs[0][b_k+2][b_n]=pb.z; Bs[0][b_k+3][b_n]=pb.w;
    __syncthreads();

    const int nit = HID / 8;
    for (int it = 0; it < nit; ++it) {
        int cur = it & 1;
        if (it + 1 < nit) {
            int k0 = (it + 1) * 8;
            pa = *(const float4*)(aptr + k0 + a_k);
            pb = *(const float4*)(bptr + k0 + b_k);
        }
#pragma unroll
        for (int kk = 0; kk < 8; ++kk) {
            float4 x0 = *(const float4*)&As[cur][kk][r0];
            float4 x1 = *(const float4*)&As[cur][kk][r0+4];
            float4 y0 = *(const float4*)&Bs[cur][kk][c0];
            float4 y1 = *(const float4*)&Bs[cur][kk][c0+4];
            float a[8] = {x0.x,x0.y,x0.z,x0.w,x1.x,x1.y,x1.z,x1.w};
            float b[8] = {y0.x,y0.y,y0.z,y0.w,y1.x,y1.y,y1.z,y1.w};
#pragma unroll
            for (int i = 0; i < 8; ++i)
#pragma unroll
                for (int j = 0; j < 8; ++j)
                    acc[i][j] = fmaf(a[i], b[j], acc[i][j]);
        }
        if (it + 1 < nit) {
            int nxt = cur ^ 1;
            As[nxt][a_k+0][a_m]=pa.x; As[nxt][a_k+1][a_m]=pa.y; As[nxt][a_k+2][a_m]=pa.z; As[nxt][a_k+3][a_m]=pa.w;
            Bs[nxt][b_k+0][b_n]=pb.x; Bs[nxt][b_k+1][b_n]=pb.y; Bs[nxt][b_k+2][b_n]=pb.z; Bs[nxt][b_k+3][b_n]=pb.w;
            __syncthreads();
        }
    }

#pragma unroll
    for (int i = 0; i < 8; ++i) {
        int m = mbase + r0 + i;
#pragma unroll
        for (int j = 0; j < 8; ++j) {
            int n = nbase + c0 + j;
            out[(size_t)m * NCLS + n] = acc[i][j] + bout[n];
        }
    }
}

// ---------------------------------------------------------------------------
extern "C" void kernel_launch(void* const* d_in, const int* in_sizes, int n_in,
                              void* d_out, int out_size)
{
    (void)in_sizes; (void)n_in; (void)out_size;
    const int*   X = (const int*)d_in[0];
    const float* C = (const float*)d_in[1];
    const float* W[8];
    const float* B[8];
    for (int i = 0; i < 8; ++i) W[i] = (const float*)d_in[2 + i];
    for (int i = 0; i < 8; ++i) B[i] = (const float*)d_in[10 + i];
    const float* Wout = (const float*)d_in[18];
    const float* bout = (const float*)d_in[19];
    float* out = (float*)d_out;

    static int smem_set = 0;
    if (!smem_set) {
        cudaFuncSetAttribute(xproj_hm, cudaFuncAttributeMaxDynamicSharedMemorySize, SMEMSZ);
        cudaFuncSetAttribute(step_hm,  cudaFuncAttributeMaxDynamicSharedMemorySize, SMEMSZ);
        smem_set = 1;
    }

    init_kernel<<<(HB2 + 255) / 256, 256>>>();
    convw_kernel<<<16384, 256>>>(W[0],W[1],W[2],W[3],W[4],W[5],W[6],W[7]);
    convc_kernel<<<NCLS, 256>>>(C);
    bias_kernel<<<(2 * G4 + 255) / 256, 256>>>(B[0],B[1],B[2],B[3],B[4],B[5],B[6],B[7]);

    xproj_hm<<<dim3(64, 512), 256, SMEMSZ>>>(X);

    for (int s = 0; s < SEQ; ++s)
        step_hm<<<dim3(32, 2, 2), 256, SMEMSZ>>>(s);

    hsum_kernel<<<(HB + 255) / 256, 256>>>();
    out_kernel<<<dim3(NCLS / 128, BATCH / 128), 256>>>(Wout, bout, out);
}

// round 6
// speedup vs baseline: 1.2707x; 1.2707x over previous
#include <cuda_runtime.h>
#include <cuda_bf16.h>
#include <math.h>
#include <stdint.h>

#define BATCH 256
#define SEQ   256
#define EMB   1024
#define HID   1024
#define NCLS  32000
#define G4    4096          // 4 gates * HID
#define WROW  2048          // EMB + HID
#define HB    (BATCH*HID)   // 262144
#define HB2   (2*BATCH*HID) // 524288 (2 dirs)
#define KS    32            // K chunk
#define NCH   32            // 1024 / 32 chunks

// xproj kernel smem layout (128x128 tile, 4-stage pipeline)
#define NSTG  4
#define STGB  8192          // 128 rows x 32 bf16 per stage
#define SMB_B 32768
#define SM_TOKS 67584
#define SMEMSZ  69632

// persistent step kernel smem layout
#define PW      68                       // pre row stride (floats), 16B aligned
#define SMP_B   0                        // 32 chunks x 4096B = 131072 (B resident)
#define SMP_A   131072                   // 3 x 16384 A buffers
#define SMP_PRE (131072 + 49152)         // 128*68*4 = 34816
#define SMEMP   (131072 + 49152 + 34816) // 215040

// Scratch (device globals: allocation-free rule)
static __device__ float          g_XWf[(size_t)2 * SEQ * BATCH * G4]; // fp32 preact+bias
static __device__ __nv_bfloat16  g_Cb[(size_t)NCLS * EMB];
static __device__ __nv_bfloat16  g_Whb[(size_t)2 * G4 * HID];   // [d][col*4+gi][k]
static __device__ __nv_bfloat16  g_Wxb[(size_t)2 * G4 * EMB];   // [d][col*4+gi][k]
static __device__ __nv_bfloat16  g_hb[2 * HB2];                 // [pingpong][dir][b][col]
static __device__ float          g_c[HB2];
static __device__ float          g_hsum[HB];
static __device__ float          g_biasI[2 * G4];
static __device__ unsigned       g_bar;                          // device-wide barrier

// ---------------------------------------------------------------------------
__device__ __forceinline__ uint32_t smem_u32(const void* p) {
    uint32_t a;
    asm("{ .reg .u64 t; cvta.to.shared.u64 t, %1; cvt.u32.u64 %0, t; }" : "=r"(a) : "l"(p));
    return a;
}
__device__ __forceinline__ void cp16(uint32_t s, const void* g) {
    asm volatile("cp.async.ca.shared.global [%0], [%1], 16;"
                 :: "r"(s), "l"(__cvta_generic_to_global(g)) : "memory");
}
__device__ __forceinline__ void cp16cg(uint32_t s, const void* g) {   // L1-bypass
    asm volatile("cp.async.cg.shared.global [%0], [%1], 16;"
                 :: "r"(s), "l"(__cvta_generic_to_global(g)) : "memory");
}
#define CP_COMMIT() asm volatile("cp.async.commit_group;" ::: "memory")
#define CP_WAIT(n)  asm volatile("cp.async.wait_group %0;" :: "n"(n) : "memory")

#define LDSM4(R, A) \
    asm volatile("ldmatrix.sync.aligned.m8n8.x4.shared.b16 {%0,%1,%2,%3}, [%4];" \
        : "=r"((R)[0]), "=r"((R)[1]), "=r"((R)[2]), "=r"((R)[3]) : "r"(A))

__device__ __forceinline__ void mma_bf16(float* d, const uint32_t* a, const uint32_t* b)
{
    asm volatile(
        "mma.sync.aligned.m16n8k16.row.col.f32.bf16.bf16.f32 "
        "{%0,%1,%2,%3}, {%4,%5,%6,%7}, {%8,%9}, {%0,%1,%2,%3};\n"
        : "+f"(d[0]), "+f"(d[1]), "+f"(d[2]), "+f"(d[3])
        : "r"(a[0]), "r"(a[1]), "r"(a[2]), "r"(a[3]), "r"(b[0]), "r"(b[1]));
}

// 16B-slot swizzle: row r, 16B-chunk c (0..3 over 32 bf16 k).
// slot byte = r*64 + ((c ^ ((r>>1)&3))<<4). Conflict-free for LDSM & STS.
__device__ __forceinline__ uint32_t slotb(int r, int c) {
    return (uint32_t)((r << 6) + ((c ^ ((r >> 1) & 3)) << 4));
}

// ---------------------------------------------------------------------------
// init / conversions
// ---------------------------------------------------------------------------
__global__ void init_kernel()
{
    int i = blockIdx.x * blockDim.x + threadIdx.x;
    if (i == 0) g_bar = 0u;
    if (i < HB2) g_c[i] = 0.f;
    if (i < HB2) reinterpret_cast<uint32_t*>(g_hb)[i] = 0u;
}

__global__ __launch_bounds__(256) void convw_kernel(
    const float* __restrict__ W0, const float* __restrict__ W1,
    const float* __restrict__ W2, const float* __restrict__ W3,
    const float* __restrict__ W4, const float* __restrict__ W5,
    const float* __restrict__ W6, const float* __restrict__ W7)
{
    const float* Ws[8] = {W0,W1,W2,W3,W4,W5,W6,W7};
    int r = blockIdx.x;             // 0..16383
    int k = threadIdx.x * 4;
    const float* src;
    __nv_bfloat16* dst;
    if (r < 8192) {
        int d = r >> 12, np = r & 4095, gi = np & 3, col = np >> 2;
        src = Ws[d*4 + gi] + (size_t)col * WROW + EMB + k;
        dst = g_Whb + (size_t)r * HID + k;
    } else {
        int rr = r - 8192;
        int d = rr >> 12, np = rr & 4095, gi = np & 3, col = np >> 2;
        src = Ws[d*4 + gi] + (size_t)col * WROW + k;
        dst = g_Wxb + (size_t)rr * EMB + k;
    }
    float4 v = *(const float4*)src;
    __nv_bfloat162 lo; lo.x = __float2bfloat16(v.x); lo.y = __float2bfloat16(v.y);
    __nv_bfloat162 hi; hi.x = __float2bfloat16(v.z); hi.y = __float2bfloat16(v.w);
    *reinterpret_cast<__nv_bfloat162*>(dst)     = lo;
    *reinterpret_cast<__nv_bfloat162*>(dst + 2) = hi;
}

__global__ __launch_bounds__(256) void convc_kernel(const float* __restrict__ C)
{
    size_t row = blockIdx.x;
    int k = threadIdx.x * 4;
    float4 v = *(const float4*)(C + row * EMB + k);
    __nv_bfloat16* dst = g_Cb + row * EMB + k;
    __nv_bfloat162 lo; lo.x = __float2bfloat16(v.x); lo.y = __float2bfloat16(v.y);
    __nv_bfloat162 hi; hi.x = __float2bfloat16(v.z); hi.y = __float2bfloat16(v.w);
    *reinterpret_cast<__nv_bfloat162*>(dst)     = lo;
    *reinterpret_cast<__nv_bfloat162*>(dst + 2) = hi;
}

__global__ void bias_kernel(
    const float* __restrict__ B0, const float* __restrict__ B1,
    const float* __restrict__ B2, const float* __restrict__ B3,
    const float* __restrict__ B4, const float* __restrict__ B5,
    const float* __restrict__ B6, const float* __restrict__ B7)
{
    const float* Bs[8] = {B0,B1,B2,B3,B4,B5,B6,B7};
    int n = blockIdx.x * blockDim.x + threadIdx.x;
    if (n < 2 * G4) {
        int d = n >> 12, rr = n & 4095, gi = rr & 3, col = rr >> 2;
        g_biasI[n] = Bs[d*4 + gi][col];
    }
}

// ---------------------------------------------------------------------------
// xproj: XWf = gathered C[X] @ Wx^T + bias (fp32 out). 128x128 tile,
// 8 warps (2m x 4n), KS=32, 4-stage cp.async, ldmatrix.
// ---------------------------------------------------------------------------
__global__ __launch_bounds__(256) void xproj_hm(const int* __restrict__ X)
{
    extern __shared__ __align__(16) char sm[];
    const uint32_t smb = smem_u32(sm);
    const int tid = threadIdx.x;
    const int lane = tid & 31, warp = tid >> 5;
    const int nbase = blockIdx.x * 128;
    const int mbase = blockIdx.y * 128;
    const int m0 = (warp >> 2) * 64, n0 = (warp & 3) * 32;

    if (tid < 128) {
        int m = mbase + tid;
        ((int*)(sm + SM_TOKS))[tid] = X[(m & 255) * SEQ + (m >> 8)];   // X[b][t]
    }
    __syncthreads();

    const __nv_bfloat16* aRow = g_Cb + (size_t)((int*)(sm + SM_TOKS))[tid >> 1] * EMB;
    const __nv_bfloat16* bRow = g_Wxb + (size_t)(nbase + (tid >> 1)) * EMB;

    float acc[16][4];
#pragma unroll
    for (int i = 0; i < 16; ++i)
#pragma unroll
        for (int j = 0; j < 4; ++j) acc[i][j] = 0.f;

    {
        const int rL = tid >> 1, cL = (tid & 1) * 2;
        const uint32_t sa0 = smb + slotb(rL, cL);
        const uint32_t sa1 = smb + slotb(rL, cL + 1);
        const uint32_t sb0 = smb + SMB_B + slotb(rL, cL);
        const uint32_t sb1 = smb + SMB_B + slotb(rL, cL + 1);
        const __nv_bfloat16* gA = aRow + cL * 8;
        const __nv_bfloat16* gB = bRow + cL * 8;

        uint32_t aAddr[4], bAddr[2];
#pragma unroll
        for (int mi = 0; mi < 4; ++mi)
            aAddr[mi] = smb + slotb(m0 + mi * 16 + (lane & 15), lane >> 4);
#pragma unroll
        for (int p = 0; p < 2; ++p)
            bAddr[p] = smb + SMB_B
                     + slotb(n0 + (2 * p + ((lane >> 4) & 1)) * 8 + (lane & 7), (lane >> 3) & 1);

#pragma unroll
        for (int st = 0; st < NSTG - 1; ++st) {
            const int kb = st * KS;
            cp16(sa0 + st * STGB, gA + kb);
            cp16(sa1 + st * STGB, gA + kb + 8);
            cp16(sb0 + st * STGB, gB + kb);
            cp16(sb1 + st * STGB, gB + kb + 8);
            CP_COMMIT();
        }

        for (int ch = 0; ch < NCH; ++ch) {
            CP_WAIT(2);
            __syncthreads();
            if (ch + NSTG - 1 < NCH) {
                const int st = (ch + NSTG - 1) & (NSTG - 1);
                const int kb = (ch + NSTG - 1) * KS;
                cp16(sa0 + st * STGB, gA + kb);
                cp16(sa1 + st * STGB, gA + kb + 8);
                cp16(sb0 + st * STGB, gB + kb);
                cp16(sb1 + st * STGB, gB + kb + 8);
            }
            CP_COMMIT();

            const uint32_t soff = (uint32_t)((ch & (NSTG - 1)) * STGB);
#pragma unroll
            for (int kk = 0; kk < 2; ++kk) {
                const uint32_t x = kk ? 32u : 0u;
                uint32_t af[4][4], bf[2][4];
#pragma unroll
                for (int mi = 0; mi < 4; ++mi) LDSM4(af[mi], (aAddr[mi] + soff) ^ x);
#pragma unroll
                for (int p = 0; p < 2; ++p)    LDSM4(bf[p], (bAddr[p] + soff) ^ x);
#pragma unroll
                for (int mi = 0; mi < 4; ++mi)
#pragma unroll
                    for (int ni = 0; ni < 4; ++ni)
                        mma_bf16(acc[mi * 4 + ni], af[mi], &bf[ni >> 1][(ni & 1) * 2]);
            }
        }
        __syncthreads();
    }

    // Epilogue: acc + bias -> g_XWf (fp32, float2 scatter)
    const int g = lane >> 2, q = lane & 3;
    const int dd = nbase >> 12;
    float2 bias2[4];
#pragma unroll
    for (int ni = 0; ni < 4; ++ni)
        bias2[ni] = *reinterpret_cast<const float2*>(
            g_biasI + (size_t)dd * G4 + (nbase & 4095) + n0 + ni * 8 + 2 * q);

#pragma unroll
    for (int mi = 0; mi < 4; ++mi) {
        int m = mbase + m0 + mi * 16 + g;
        int t = m >> 8, b = m & 255;
        size_t rowbase = ((size_t)(dd * SEQ + t) * BATCH + b) * G4 + (nbase & 4095);
#pragma unroll
        for (int ni = 0; ni < 4; ++ni) {
            size_t off = rowbase + n0 + ni * 8 + 2 * q;
            float2 v0, v1;
            v0.x = acc[mi*4+ni][0] + bias2[ni].x;
            v0.y = acc[mi*4+ni][1] + bias2[ni].y;
            v1.x = acc[mi*4+ni][2] + bias2[ni].x;
            v1.y = acc[mi*4+ni][3] + bias2[ni].y;
            *reinterpret_cast<float2*>(g_XWf + off)          = v0;   // row b
            *reinterpret_cast<float2*>(g_XWf + off + 8 * G4) = v1;   // row b+8
        }
    }
}

// ---------------------------------------------------------------------------
// Persistent recurrence: one launch, all 256 steps, device-wide barrier.
// Grid (64, 2): 64 N-tiles of 64 gate-cols x 2 dirs = 128 CTAs (1/SM).
// Per CTA: B tile (64x1024 bf16) resident in smem for all steps;
// A (h_t, 256x1024 bf16) streamed per step via cp.async.cg (L1-bypass).
// 8 warps: 4 m-split (64 rows) x 2 n-split (32 cols); acc 16x4.
// ---------------------------------------------------------------------------
__global__ __launch_bounds__(256) void step_persist()
{
    extern __shared__ __align__(16) char sm[];
    const uint32_t smb = smem_u32(sm);
    const int tid = threadIdx.x;
    const int lane = tid & 31, warp = tid >> 5;
    const int d = blockIdx.y;
    const int nbase = blockIdx.x * 64;        // over G4
    const int m0 = (warp >> 1) * 64, n0 = (warp & 1) * 32;
    float* pre = reinterpret_cast<float*>(sm + SMP_PRE);
    const unsigned NCTA = gridDim.x * gridDim.y;

    // ---- Preload B once: 32 chunks x (64 rows x 32 k), swizzled
    {
        const __nv_bfloat16* Bg = g_Whb + ((size_t)d * G4 + nbase) * HID;
#pragma unroll
        for (int v = 0; v < 32; ++v) {
            int j = v * 256 + tid;             // 16B-group index 0..8191
            int ch = j >> 8, s2 = j & 255;
            int r = s2 >> 2, c = s2 & 3;
            cp16(smb + SMP_B + ch * 4096 + slotb(r, c),
                 Bg + (size_t)r * HID + ch * 32 + c * 8);
        }
        CP_COMMIT();
        CP_WAIT(0);
        __syncthreads();
    }

    // LDSM fragment addresses
    uint32_t aAddr[4], bAddr[2];
#pragma unroll
    for (int mi = 0; mi < 4; ++mi)
        aAddr[mi] = smb + SMP_A + slotb(m0 + mi * 16 + (lane & 15), lane >> 4);
#pragma unroll
    for (int p = 0; p < 2; ++p)
        bAddr[p] = smb + SMP_B
                 + slotb(n0 + (2 * p + ((lane >> 4) & 1)) * 8 + (lane & 7), (lane >> 3) & 1);

    // A-loader slots: thread covers rows rA, rA+64, rA+128, rA+192 at chunk c
    const int rA = tid >> 2, cA = tid & 3;
    uint32_t aDst[4];
#pragma unroll
    for (int v = 0; v < 4; ++v)
        aDst[v] = smb + SMP_A + slotb((v << 6) + rA, cA);

    for (int s = 0; s < SEQ; ++s) {
        const int rb = s & 1, wb = rb ^ 1;
        const __nv_bfloat16* gA = g_hb + (size_t)rb * HB2 + (size_t)d * HB
                                       + (size_t)rA * HID + cA * 8;

        // Prologue: chunks 0,1 -> buffers 0,1
#pragma unroll
        for (int st = 0; st < 2; ++st) {
#pragma unroll
            for (int v = 0; v < 4; ++v)
                cp16cg(aDst[v] + st * 16384, gA + (size_t)(v << 6) * HID + st * KS);
            CP_COMMIT();
        }

        float acc[16][4];
#pragma unroll
        for (int i = 0; i < 16; ++i)
#pragma unroll
            for (int j = 0; j < 4; ++j) acc[i][j] = 0.f;

        int buf = 0, nxt = 2;
        for (int ch = 0; ch < NCH; ++ch) {
            CP_WAIT(1);
            __syncthreads();
            if (ch + 2 < NCH) {
#pragma unroll
                for (int v = 0; v < 4; ++v)
                    cp16cg(aDst[v] + nxt * 16384,
                           gA + (size_t)(v << 6) * HID + (ch + 2) * KS);
            }
            CP_COMMIT();

            const uint32_t aoff = (uint32_t)(buf * 16384);
            const uint32_t boff = (uint32_t)(ch * 4096);
#pragma unroll
            for (int kk = 0; kk < 2; ++kk) {
                const uint32_t x = kk ? 32u : 0u;
                uint32_t af[4][4], bf[2][4];
#pragma unroll
                for (int mi = 0; mi < 4; ++mi) LDSM4(af[mi], (aAddr[mi] + aoff) ^ x);
#pragma unroll
                for (int p = 0; p < 2; ++p)    LDSM4(bf[p], (bAddr[p] + boff) ^ x);
#pragma unroll
                for (int mi = 0; mi < 4; ++mi)
#pragma unroll
                    for (int ni = 0; ni < 4; ++ni)
                        mma_bf16(acc[mi * 4 + ni], af[mi], &bf[ni >> 1][(ni & 1) * 2]);
            }
            buf = (buf == 2) ? 0 : buf + 1;
            nxt = (nxt == 2) ? 0 : nxt + 1;
        }
        __syncthreads();

        // ---- Fused LSTM cell epilogue, two 128-row halves
        const int tt = d ? (SEQ - 1 - s) : s;
        const int g = lane >> 2, q = lane & 3;
#pragma unroll
        for (int hh = 0; hh < 2; ++hh) {
            if ((m0 < 128) == (hh == 0)) {
                const int rbase = m0 - hh * 128;
#pragma unroll
                for (int mi = 0; mi < 4; ++mi)
#pragma unroll
                    for (int half = 0; half < 2; ++half) {
                        int r = rbase + mi * 16 + g + half * 8;
#pragma unroll
                        for (int ni = 0; ni < 4; ++ni) {
                            int c = n0 + ni * 8 + 2 * q;
                            *reinterpret_cast<float2*>(&pre[r * PW + c]) =
                                make_float2(acc[mi*4+ni][half*2], acc[mi*4+ni][half*2+1]);
                        }
                    }
            }
            __syncthreads();
            {
                const int r = tid & 127, hc = tid >> 7;
                const int b = hh * 128 + r;
                const float* prow = pre + r * PW + hc * 32;
                const float* xwp = g_XWf + ((size_t)(d * SEQ + tt) * BATCH + b) * G4
                                         + nbase + hc * 32;
                float* cptr = g_c + (size_t)d * HB + (size_t)b * HID + (nbase >> 2) + hc * 8;
                __nv_bfloat16* hp = g_hb + (size_t)wb * HB2 + (size_t)d * HB
                                         + (size_t)b * HID + (nbase >> 2) + hc * 8;
                float4 cv0 = *reinterpret_cast<const float4*>(cptr);
                float4 cv1 = *reinterpret_cast<const float4*>(cptr + 4);
                float cold[8] = {cv0.x, cv0.y, cv0.z, cv0.w, cv1.x, cv1.y, cv1.z, cv1.w};
                float cnew[8];
                uint32_t hbuf[4];
#pragma unroll
                for (int j = 0; j < 8; ++j) {
                    float4 p  = *reinterpret_cast<const float4*>(prow + 4 * j);
                    float4 xw = *reinterpret_cast<const float4*>(xwp + 4 * j);
                    float pi = p.x + xw.x;
                    float pf = p.y + xw.y;
                    float po = p.z + xw.z;
                    float pg = p.w + xw.w;
                    float ig = 1.f / (1.f + expf(-pi));
                    float fg = 1.f / (1.f + expf(-pf));
                    float og = 1.f / (1.f + expf(-po));
                    float gv = tanhf(pg);
                    float cc = fg * cold[j] + ig * gv;
                    cnew[j] = cc;
                    float hv = og * tanhf(cc);
                    __nv_bfloat16 hb16 = __float2bfloat16(hv);
                    uint16_t raw = *reinterpret_cast<uint16_t*>(&hb16);
                    if (j & 1) hbuf[j >> 1] |= ((uint32_t)raw) << 16;
                    else       hbuf[j >> 1]  = raw;
                }
                *reinterpret_cast<float4*>(cptr)     = make_float4(cnew[0], cnew[1], cnew[2], cnew[3]);
                *reinterpret_cast<float4*>(cptr + 4) = make_float4(cnew[4], cnew[5], cnew[6], cnew[7]);
                *reinterpret_cast<uint4*>(hp) = *reinterpret_cast<uint4*>(hbuf);
            }
            __syncthreads();
        }

        // ---- Device-wide barrier (all h writes visible before next step)
        if (tid == 0) {
            __threadfence();
            asm volatile("red.release.gpu.global.add.u32 [%0], 1;"
                         :: "l"(&g_bar) : "memory");
            const unsigned target = NCTA * (unsigned)(s + 1);
            unsigned v;
            do {
                asm volatile("ld.acquire.gpu.global.u32 %0, [%1];"
                             : "=r"(v) : "l"(&g_bar) : "memory");
            } while (v < target);
        }
        __syncthreads();
    }
}

// ---------------------------------------------------------------------------
__global__ void hsum_kernel()
{
    int i = blockIdx.x * blockDim.x + threadIdx.x;
    if (i < HB)
        g_hsum[i] = __bfloat162float(g_hb[i]) + __bfloat162float(g_hb[HB + i]);
}

// ---------------------------------------------------------------------------
// Output GEMM in fp32 FFMA (precision): M=256, N=32000, K=1024.
// ---------------------------------------------------------------------------
__global__ __launch_bounds__(256) void out_kernel(
    const float* __restrict__ Wout, const float* __restrict__ bout,
    float* __restrict__ out)
{
    __shared__ __align__(16) float As[2][8][128];
    __shared__ __align__(16) float Bs[2][8][128];

    const int tid   = threadIdx.x;
    const int nbase = blockIdx.x * 128;
    const int mbase = blockIdx.y * 128;

    const int a_m = tid >> 1, a_k = (tid & 1) * 4;
    const int b_n = tid >> 1, b_k = (tid & 1) * 4;
    const float* aptr = g_hsum + (size_t)(mbase + a_m) * HID;
    const float* bptr = Wout + (size_t)(nbase + b_n) * HID;

    float acc[8][8];
#pragma unroll
    for (int i = 0; i < 8; ++i)
#pragma unroll
        for (int j = 0; j < 8; ++j) acc[i][j] = 0.f;

    const int r0 = (tid >> 4) * 8;
    const int c0 = (tid & 15) * 8;

    float4 pa = *(const float4*)(aptr + a_k);
    float4 pb = *(const float4*)(bptr + b_k);
    As[0][a_k+0][a_m]=pa.x; As[0][a_k+1][a_m]=pa.y; As[0][a_k+2][a_m]=pa.z; As[0][a_k+3][a_m]=pa.w;
    Bs[0][b_k+0][b_n]=pb.x; Bs[0][b_k+1][b_n]=pb.y; Bs[0][b_k+2][b_n]=pb.z; Bs[0][b_k+3][b_n]=pb.w;
    __syncthreads();

    const int nit = HID / 8;
    for (int it = 0; it < nit; ++it) {
        int cur = it & 1;
        if (it + 1 < nit) {
            int k0 = (it + 1) * 8;
            pa = *(const float4*)(aptr + k0 + a_k);
            pb = *(const float4*)(bptr + k0 + b_k);
        }
#pragma unroll
        for (int kk = 0; kk < 8; ++kk) {
            float4 x0 = *(const float4*)&As[cur][kk][r0];
            float4 x1 = *(const float4*)&As[cur][kk][r0+4];
            float4 y0 = *(const float4*)&Bs[cur][kk][c0];
            float4 y1 = *(const float4*)&Bs[cur][kk][c0+4];
            float a[8] = {x0.x,x0.y,x0.z,x0.w,x1.x,x1.y,x1.z,x1.w};
            float b[8] = {y0.x,y0.y,y0.z,y0.w,y1.x,y1.y,y1.z,y1.w};
#pragma unroll
            for (int i = 0; i < 8; ++i)
#pragma unroll
                for (int j = 0; j < 8; ++j)
                    acc[i][j] = fmaf(a[i], b[j], acc[i][j]);
        }
        if (it + 1 < nit) {
            int nxt = cur ^ 1;
            As[nxt][a_k+0][a_m]=pa.x; As[nxt][a_k+1][a_m]=pa.y; As[nxt][a_k+2][a_m]=pa.z; As[nxt][a_k+3][a_m]=pa.w;
            Bs[nxt][b_k+0][b_n]=pb.x; Bs[nxt][b_k+1][b_n]=pb.y; Bs[nxt][b_k+2][b_n]=pb.z; Bs[nxt][b_k+3][b_n]=pb.w;
            __syncthreads();
        }
    }

#pragma unroll
    for (int i = 0; i < 8; ++i) {
        int m = mbase + r0 + i;
#pragma unroll
        for (int j = 0; j < 8; ++j) {
            int n = nbase + c0 + j;
            out[(size_t)m * NCLS + n] = acc[i][j] + bout[n];
        }
    }
}

// ---------------------------------------------------------------------------
extern "C" void kernel_launch(void* const* d_in, const int* in_sizes, int n_in,
                              void* d_out, int out_size)
{
    (void)in_sizes; (void)n_in; (void)out_size;
    const int*   X = (const int*)d_in[0];
    const float* C = (const float*)d_in[1];
    const float* W[8];
    const float* B[8];
    for (int i = 0; i < 8; ++i) W[i] = (const float*)d_in[2 + i];
    for (int i = 0; i < 8; ++i) B[i] = (const float*)d_in[10 + i];
    const float* Wout = (const float*)d_in[18];
    const float* bout = (const float*)d_in[19];
    float* out = (float*)d_out;

    static int smem_set = 0;
    if (!smem_set) {
        cudaFuncSetAttribute(xproj_hm, cudaFuncAttributeMaxDynamicSharedMemorySize, SMEMSZ);
        cudaFuncSetAttribute(step_persist, cudaFuncAttributeMaxDynamicSharedMemorySize, SMEMP);
        smem_set = 1;
    }

    init_kernel<<<(HB2 + 255) / 256, 256>>>();
    convw_kernel<<<16384, 256>>>(W[0],W[1],W[2],W[3],W[4],W[5],W[6],W[7]);
    convc_kernel<<<NCLS, 256>>>(C);
    bias_kernel<<<(2 * G4 + 255) / 256, 256>>>(B[0],B[1],B[2],B[3],B[4],B[5],B[6],B[7]);

    // Input projections (tensor cores).
    xproj_hm<<<dim3(64, 512), 256, SMEMSZ>>>(X);

    // Entire recurrence: ONE persistent kernel, 128 co-resident CTAs.
    step_persist<<<dim3(64, 2), 256, SMEMP>>>();

    hsum_kernel<<<(HB + 255) / 256, 256>>>();
    out_kernel<<<dim3(NCLS / 128, BATCH / 128), 256>>>(Wout, bout, out);
}